// round 6
// baseline (speedup 1.0000x reference)
#include <cuda_runtime.h>
#include <cuda_fp16.h>
#include <cstdint>

// ===================== problem constants =====================
static constexpr int M_TOTAL = 8192;     // B*S = 4*2048 tokens
static constexpr int N_TOTAL = 4096;     // out_features
static constexpr int K_TOTAL = 4096;     // in_features
static constexpr int GROUPS  = 131072;   // out*in/group_size

// ===================== GEMM tiling =====================
static constexpr int BM = 128;
static constexpr int BN = 128;
static constexpr int BK = 64;                       // fp16 elems; 128B row -> SW128 atom
static constexpr int NUM_K  = K_TOTAL / BK;         // 64
static constexpr int STAGES = 4;

static constexpr int A_BYTES     = BM * 128;        // 16 KB
static constexpr int B_BYTES     = BN * 128;        // 16 KB
static constexpr int STAGE_BYTES = A_BYTES + B_BYTES;  // 32 KB
static constexpr int SMEM_TOTAL  = 1024 + STAGES * STAGE_BYTES;  // 129 KB

// ===================== scratch (no allocation allowed) =====================
__device__ __half g_x16[(size_t)M_TOTAL * K_TOTAL];   // 64 MB
__device__ __half g_w16[(size_t)N_TOTAL * K_TOTAL];   // 32 MB
__device__ float  g_blend[GROUPS];                    // 0.5 MB

// ===================== PTX helpers (baseline sm_80-class only) =====================
__device__ __forceinline__ uint32_t smem_u32(const void* p) {
    uint32_t a;
    asm("{ .reg .u64 t; cvta.to.shared.u64 t, %1; cvt.u32.u64 %0, t; }" : "=r"(a) : "l"(p));
    return a;
}
__device__ __forceinline__ void cp_async16(uint32_t dst, const void* src) {
    asm volatile("cp.async.cg.shared.global [%0], [%1], 16;" :: "r"(dst), "l"(src));
}
__device__ __forceinline__ void cp_commit() {
    asm volatile("cp.async.commit_group;" ::: "memory");
}
__device__ __forceinline__ void cp_wait_2() {
    asm volatile("cp.async.wait_group 2;" ::: "memory");
}

#define LDMATRIX_X4(r0, r1, r2, r3, addr) \
    asm volatile("ldmatrix.sync.aligned.m8n8.x4.shared.b16 {%0,%1,%2,%3}, [%4];" \
                 : "=r"(r0), "=r"(r1), "=r"(r2), "=r"(r3) : "r"(addr))

__device__ __forceinline__ void mma16816(float* c, const uint32_t* a, const uint32_t* b) {
    asm volatile(
        "mma.sync.aligned.m16n8k16.row.col.f32.f16.f16.f32 "
        "{%0,%1,%2,%3}, {%4,%5,%6,%7}, {%8,%9}, {%0,%1,%2,%3};"
        : "+f"(c[0]), "+f"(c[1]), "+f"(c[2]), "+f"(c[3])
        : "r"(a[0]), "r"(a[1]), "r"(a[2]), "r"(a[3]), "r"(b[0]), "r"(b[1]));
}

// SW128: cols < 128B so the xor value depends only on row&7
#define SW128(off) ((off) ^ (((off) >> 3) & 0x70))

// ===================== prep kernels =====================
__global__ void blend_kernel(const float* __restrict__ ps, const float* __restrict__ routing) {
    __shared__ float r[8];
    if (threadIdx.x < 8) r[threadIdx.x] = routing[threadIdx.x];
    __syncthreads();
    int g = blockIdx.x * blockDim.x + threadIdx.x;
    if (g < GROUPS) {
        float acc = 0.f;
#pragma unroll
        for (int p = 0; p < 8; p++) acc = fmaf(r[p], ps[(size_t)p * GROUPS + g], acc);
        g_blend[g] = acc;
    }
}

__global__ void convert_x_kernel(const float4* __restrict__ x) {
    size_t i = (size_t)blockIdx.x * blockDim.x + threadIdx.x;   // one float4 each
    const size_t n4 = (size_t)M_TOTAL * K_TOTAL / 4;
    if (i < n4) {
        float4 v = x[i];
        __half2* o = (__half2*)g_x16;
        o[2 * i]     = __floats2half2_rn(v.x, v.y);
        o[2 * i + 1] = __floats2half2_rn(v.z, v.w);
    }
}

__global__ void build_w_kernel(const float4* __restrict__ signs) {
    size_t i = (size_t)blockIdx.x * blockDim.x + threadIdx.x;   // one float4 each
    const size_t n4 = (size_t)N_TOTAL * K_TOTAL / 4;
    if (i < n4) {
        float4 s = signs[i];
        size_t e = i * 4;                 // e = o*4096 + c ; group = e >> 7
        float sc = g_blend[e >> 7];
        __half2* o = (__half2*)g_w16;
        o[2 * i]     = __floats2half2_rn(s.x * sc, s.y * sc);
        o[2 * i + 1] = __floats2half2_rn(s.z * sc, s.w * sc);
    }
}

// ===================== main GEMM kernel =====================
// 256 threads = 8 warps (warp_m in {0,1}, warp_n in {0..3}); warp tile 64x32.
// Both A ([m][k]) and B ([n][k]) are K-major fp16 -> ldmatrix non-trans for both,
// mma.m16n8k16.row.col with f32 accumulation.
__device__ __forceinline__ void load_tiles(uint32_t a_s, uint32_t b_s,
                                           const __half* __restrict__ Ag,
                                           const __half* __restrict__ Bg,
                                           int kelem, int tid) {
#pragma unroll
    for (int t = 0; t < 4; t++) {        // A: 128 rows x 8 chunks(16B) = 1024 chunks
        int id = t * 256 + tid;
        int r = id >> 3, c = id & 7;
        uint32_t off = (uint32_t)(r * 128 + c * 16);
        cp_async16(a_s + SW128(off), Ag + (size_t)r * K_TOTAL + kelem + c * 8);
    }
#pragma unroll
    for (int t = 0; t < 4; t++) {        // B: 128 rows x 8 chunks
        int id = t * 256 + tid;
        int r = id >> 3, c = id & 7;
        uint32_t off = (uint32_t)(r * 128 + c * 16);
        cp_async16(b_s + SW128(off), Bg + (size_t)r * K_TOTAL + kelem + c * 8);
    }
}

__global__ void __launch_bounds__(256, 1)
gemm_kernel(float* __restrict__ out) {
    extern __shared__ char smem[];
    uint32_t raw  = smem_u32(smem);
    uint32_t base = (raw + 1023) & ~1023u;              // 1024-aligned tile area

    const int tid  = threadIdx.x;
    const int wid  = tid >> 5;
    const int lane = tid & 31;
    const int warp_m = wid & 1;          // 2 warps along M
    const int warp_n = wid >> 1;         // 4 warps along N

    const int m_blk = blockIdx.y * BM;
    const int n_blk = blockIdx.x * BN;

    const __half* Ag = g_x16 + (size_t)m_blk * K_TOTAL;
    const __half* Bg = g_w16 + (size_t)n_blk * K_TOTAL;

    float acc[4][4][4];
#pragma unroll
    for (int i = 0; i < 4; i++)
#pragma unroll
        for (int j = 0; j < 4; j++)
#pragma unroll
            for (int v = 0; v < 4; v++) acc[i][j][v] = 0.f;

    // prologue: fill STAGES-1 stages
#pragma unroll
    for (int s = 0; s < STAGES - 1; s++) {
        load_tiles(base + s * STAGE_BYTES, base + s * STAGE_BYTES + A_BYTES,
                   Ag, Bg, s * BK, tid);
        cp_commit();
    }

    // per-thread ldmatrix row indices (column part varies per kstep)
    const int a_row = warp_m * 64 + (lane & 15);          // + mi*16
    const int a_csel = (lane >> 4) * 16;                  // 0 or 16 bytes
    const int b_row = warp_n * 32 + ((lane >> 4) << 3) + (lane & 7);  // + nj*16
    const int b_csel = ((lane >> 3) & 1) * 16;            // 0 or 16 bytes

    for (int k = 0; k < NUM_K; k++) {
        const int st = k & (STAGES - 1);
        cp_wait_2();                      // stage k resident
        __syncthreads();                  // all warps see data; all done with stage (k-1)

        // prefetch next stage (overwrites stage k-1, freed by the barrier above)
        const int nk = k + STAGES - 1;
        if (nk < NUM_K) {
            const int nst = nk & (STAGES - 1);
            load_tiles(base + nst * STAGE_BYTES, base + nst * STAGE_BYTES + A_BYTES,
                       Ag, Bg, nk * BK, tid);
        }
        cp_commit();                      // empty groups in tail keep counts consistent

        const uint32_t a_s = base + st * STAGE_BYTES;
        const uint32_t b_s = a_s + A_BYTES;

#pragma unroll
        for (int ks = 0; ks < 4; ks++) {
            const int kb = ks * 32;       // byte offset along K
            uint32_t afr[4][4];
#pragma unroll
            for (int mi = 0; mi < 4; mi++) {
                int row = a_row + mi * 16;
                int col = kb + a_csel;
                uint32_t addr = a_s + (uint32_t)(row * 128) + (uint32_t)(col ^ ((row & 7) << 4));
                LDMATRIX_X4(afr[mi][0], afr[mi][1], afr[mi][2], afr[mi][3], addr);
            }
            uint32_t bfr[4][2];
#pragma unroll
            for (int nj = 0; nj < 2; nj++) {
                int row = b_row + nj * 16;
                int col = kb + b_csel;
                uint32_t addr = b_s + (uint32_t)(row * 128) + (uint32_t)(col ^ ((row & 7) << 4));
                uint32_t r0, r1, r2, r3;
                LDMATRIX_X4(r0, r1, r2, r3, addr);
                bfr[nj * 2][0] = r0; bfr[nj * 2][1] = r1;       // n8 block nj*2
                bfr[nj * 2 + 1][0] = r2; bfr[nj * 2 + 1][1] = r3; // n8 block nj*2+1
            }
#pragma unroll
            for (int mi = 0; mi < 4; mi++)
#pragma unroll
                for (int ni = 0; ni < 4; ni++)
                    mma16816(acc[mi][ni], afr[mi], bfr[ni]);
        }
    }

    // ===================== epilogue =====================
    // mma frag layout: c0,c1 -> (row = lane>>2, cols = 2*(lane&3), +1); c2,c3 -> row+8
    const int m0 = m_blk + warp_m * 64 + (lane >> 2);
    const int n0 = n_blk + warp_n * 32 + (lane & 3) * 2;
#pragma unroll
    for (int mi = 0; mi < 4; mi++) {
#pragma unroll
        for (int ni = 0; ni < 4; ni++) {
            float* p0 = out + (size_t)(m0 + mi * 16) * N_TOTAL + n0 + ni * 8;
            float* p1 = p0 + 8 * N_TOTAL;
            *(float2*)p0 = make_float2(acc[mi][ni][0], acc[mi][ni][1]);
            *(float2*)p1 = make_float2(acc[mi][ni][2], acc[mi][ni][3]);
        }
    }
}

// ===================== launch =====================
extern "C" void kernel_launch(void* const* d_in, const int* in_sizes, int n_in,
                              void* d_out, int out_size) {
    const float* x       = (const float*)d_in[0];   // [8192, 4096] f32
    const float* signs   = (const float*)d_in[1];   // [4096, 4096] f32 (+-1)
    const float* ps      = (const float*)d_in[2];   // [8, 131072]  f32
    const float* routing = (const float*)d_in[3];   // [8]          f32
    float* out = (float*)d_out;                     // [8192, 4096] f32

    blend_kernel<<<GROUPS / 256, 256>>>(ps, routing);
    convert_x_kernel<<<(int)(((size_t)M_TOTAL * K_TOTAL / 4) / 256), 256>>>((const float4*)x);
    build_w_kernel<<<(int)(((size_t)N_TOTAL * K_TOTAL / 4) / 256), 256>>>((const float4*)signs);

    cudaFuncSetAttribute(gemm_kernel, cudaFuncAttributeMaxDynamicSharedMemorySize, SMEM_TOTAL);
    gemm_kernel<<<dim3(N_TOTAL / BN, M_TOTAL / BM, 1), 256, SMEM_TOTAL>>>(out);
}

// round 7
// speedup vs baseline: 1.1079x; 1.1079x over previous
#include <cuda_runtime.h>
#include <cuda_fp16.h>
#include <cstdint>

// ===================== problem constants =====================
static constexpr int M_TOTAL = 8192;     // B*S = 4*2048 tokens
static constexpr int N_TOTAL = 4096;     // out_features
static constexpr int K_TOTAL = 4096;     // in_features
static constexpr int GROUPS  = 131072;   // out*in/group_size

// ===================== GEMM tiling =====================
static constexpr int BM = 128;
static constexpr int BN = 256;
static constexpr int BK = 64;                       // fp16 elems; 128B row -> SW128 atom
static constexpr int NUM_K  = K_TOTAL / BK;         // 64
static constexpr int STAGES = 4;

static constexpr int A_BYTES     = BM * 128;        // 16 KB
static constexpr int B_BYTES     = BN * 128;        // 32 KB
static constexpr int STAGE_BYTES = A_BYTES + B_BYTES;  // 48 KB
static constexpr int SMEM_TOTAL  = 1024 + STAGES * STAGE_BYTES;  // ~193 KB

// ===================== scratch (no allocation allowed) =====================
__device__ __half g_x16[(size_t)M_TOTAL * K_TOTAL];   // 64 MB
__device__ __half g_w16[(size_t)N_TOTAL * K_TOTAL];   // 32 MB
__device__ float  g_blend[GROUPS];                    // 0.5 MB

// ===================== PTX helpers (baseline sm_80-class only) =====================
__device__ __forceinline__ uint32_t smem_u32(const void* p) {
    uint32_t a;
    asm("{ .reg .u64 t; cvta.to.shared.u64 t, %1; cvt.u32.u64 %0, t; }" : "=r"(a) : "l"(p));
    return a;
}
__device__ __forceinline__ void cp_async16(uint32_t dst, const void* src) {
    asm volatile("cp.async.cg.shared.global [%0], [%1], 16;" :: "r"(dst), "l"(src));
}
__device__ __forceinline__ void cp_commit() {
    asm volatile("cp.async.commit_group;" ::: "memory");
}
__device__ __forceinline__ void cp_wait_2() {
    asm volatile("cp.async.wait_group 2;" ::: "memory");
}

#define LDMATRIX_X4(r0, r1, r2, r3, addr) \
    asm volatile("ldmatrix.sync.aligned.m8n8.x4.shared.b16 {%0,%1,%2,%3}, [%4];" \
                 : "=r"(r0), "=r"(r1), "=r"(r2), "=r"(r3) : "r"(addr))

__device__ __forceinline__ void mma16816(float* c, const uint32_t* a, const uint32_t* b) {
    asm volatile(
        "mma.sync.aligned.m16n8k16.row.col.f32.f16.f16.f32 "
        "{%0,%1,%2,%3}, {%4,%5,%6,%7}, {%8,%9}, {%0,%1,%2,%3};"
        : "+f"(c[0]), "+f"(c[1]), "+f"(c[2]), "+f"(c[3])
        : "r"(a[0]), "r"(a[1]), "r"(a[2]), "r"(a[3]), "r"(b[0]), "r"(b[1]));
}

// SW128: cols < 128B so the xor value depends only on row&7
#define SW128(off) ((off) ^ (((off) >> 3) & 0x70))

// ===================== prep kernels =====================
__global__ void blend_kernel(const float* __restrict__ ps, const float* __restrict__ routing) {
    __shared__ float r[8];
    if (threadIdx.x < 8) r[threadIdx.x] = routing[threadIdx.x];
    __syncthreads();
    int g = blockIdx.x * blockDim.x + threadIdx.x;
    if (g < GROUPS) {
        float acc = 0.f;
#pragma unroll
        for (int p = 0; p < 8; p++) acc = fmaf(r[p], ps[(size_t)p * GROUPS + g], acc);
        g_blend[g] = acc;
    }
}

__global__ void convert_x_kernel(const float4* __restrict__ x) {
    size_t i = (size_t)blockIdx.x * blockDim.x + threadIdx.x;   // one float4 each
    const size_t n4 = (size_t)M_TOTAL * K_TOTAL / 4;
    if (i < n4) {
        float4 v = x[i];
        __half2* o = (__half2*)g_x16;
        o[2 * i]     = __floats2half2_rn(v.x, v.y);
        o[2 * i + 1] = __floats2half2_rn(v.z, v.w);
    }
}

__global__ void build_w_kernel(const float4* __restrict__ signs) {
    size_t i = (size_t)blockIdx.x * blockDim.x + threadIdx.x;   // one float4 each
    const size_t n4 = (size_t)N_TOTAL * K_TOTAL / 4;
    if (i < n4) {
        float4 s = signs[i];
        size_t e = i * 4;                 // e = o*4096 + c ; group = e >> 7
        float sc = g_blend[e >> 7];
        __half2* o = (__half2*)g_w16;
        o[2 * i]     = __floats2half2_rn(s.x * sc, s.y * sc);
        o[2 * i + 1] = __floats2half2_rn(s.z * sc, s.w * sc);
    }
}

// ===================== main GEMM kernel =====================
// 256 threads = 8 warps (warp_m in {0,1}, warp_n in {0..3}); warp tile 64x64.
// Both A ([m][k]) and B ([n][k]) K-major fp16 -> ldmatrix non-trans for both,
// mma.m16n8k16.row.col, f32 accumulation. Fragments double-buffered across ksteps.
__device__ __forceinline__ void load_tiles(uint32_t a_s, uint32_t b_s,
                                           const __half* __restrict__ Ag,
                                           const __half* __restrict__ Bg,
                                           int kelem, int tid) {
#pragma unroll
    for (int t = 0; t < 4; t++) {        // A: 128 rows x 8 chunks(16B) = 1024 chunks
        int id = t * 256 + tid;
        int r = id >> 3, c = id & 7;
        uint32_t off = (uint32_t)(r * 128 + c * 16);
        cp_async16(a_s + SW128(off), Ag + (size_t)r * K_TOTAL + kelem + c * 8);
    }
#pragma unroll
    for (int t = 0; t < 8; t++) {        // B: 256 rows x 8 chunks = 2048 chunks
        int id = t * 256 + tid;
        int r = id >> 3, c = id & 7;
        uint32_t off = (uint32_t)(r * 128 + c * 16);
        cp_async16(b_s + SW128(off), Bg + (size_t)r * K_TOTAL + kelem + c * 8);
    }
}

__global__ void __launch_bounds__(256, 1)
gemm_kernel(float* __restrict__ out) {
    extern __shared__ char smem[];
    uint32_t raw  = smem_u32(smem);
    uint32_t base = (raw + 1023) & ~1023u;              // 1024-aligned tile area

    const int tid  = threadIdx.x;
    const int wid  = tid >> 5;
    const int lane = tid & 31;
    const int warp_m = wid & 1;          // 2 warps along M (64 rows each)
    const int warp_n = wid >> 1;         // 4 warps along N (64 cols each)

    const int m_blk = blockIdx.y * BM;
    const int n_blk = blockIdx.x * BN;

    const __half* Ag = g_x16 + (size_t)m_blk * K_TOTAL;
    const __half* Bg = g_w16 + (size_t)n_blk * K_TOTAL;

    float acc[4][8][4];
#pragma unroll
    for (int i = 0; i < 4; i++)
#pragma unroll
        for (int j = 0; j < 8; j++)
#pragma unroll
            for (int v = 0; v < 4; v++) acc[i][j][v] = 0.f;

    // prologue: fill STAGES-1 stages
#pragma unroll
    for (int s = 0; s < STAGES - 1; s++) {
        load_tiles(base + s * STAGE_BYTES, base + s * STAGE_BYTES + A_BYTES,
                   Ag, Bg, s * BK, tid);
        cp_commit();
    }

    // per-thread ldmatrix row indices (column byte varies per kstep)
    const int a_row  = warp_m * 64 + (lane & 15);                     // + mi*16
    const int a_csel = (lane >> 4) * 16;                              // 0 or 16 bytes
    const int b_row  = warp_n * 64 + ((lane >> 4) << 3) + (lane & 7); // + nj*16
    const int b_csel = ((lane >> 3) & 1) * 16;                        // 0 or 16 bytes

    uint32_t afr[2][4][4];
    uint32_t bfr[2][8][2];

    for (int k = 0; k < NUM_K; k++) {
        const int st = k & (STAGES - 1);
        cp_wait_2();                      // stage k resident
        __syncthreads();                  // all warps done with stage (k-1)

        // prefetch next stage (overwrites stage k-1, freed by the barrier above)
        const int nk = k + STAGES - 1;
        if (nk < NUM_K) {
            const int nst = nk & (STAGES - 1);
            load_tiles(base + nst * STAGE_BYTES, base + nst * STAGE_BYTES + A_BYTES,
                       Ag, Bg, nk * BK, tid);
        }
        cp_commit();                      // empty groups in tail keep counts consistent

        const uint32_t a_s = base + st * STAGE_BYTES;
        const uint32_t b_s = a_s + A_BYTES;

        // load fragments for kstep 0 into buffer 0
#pragma unroll
        for (int mi = 0; mi < 4; mi++) {
            int row = a_row + mi * 16;
            uint32_t addr = a_s + (uint32_t)(row * 128) + (uint32_t)((a_csel) ^ ((row & 7) << 4));
            LDMATRIX_X4(afr[0][mi][0], afr[0][mi][1], afr[0][mi][2], afr[0][mi][3], addr);
        }
#pragma unroll
        for (int nj = 0; nj < 4; nj++) {
            int row = b_row + nj * 16;
            uint32_t addr = b_s + (uint32_t)(row * 128) + (uint32_t)((b_csel) ^ ((row & 7) << 4));
            uint32_t r0, r1, r2, r3;
            LDMATRIX_X4(r0, r1, r2, r3, addr);
            bfr[0][nj * 2][0] = r0;     bfr[0][nj * 2][1] = r1;
            bfr[0][nj * 2 + 1][0] = r2; bfr[0][nj * 2 + 1][1] = r3;
        }

#pragma unroll
        for (int ks = 0; ks < 4; ks++) {
            const int cur = ks & 1;
            const int nxt = cur ^ 1;
            if (ks < 3) {
                const int kb = (ks + 1) * 32;   // byte offset along K
#pragma unroll
                for (int mi = 0; mi < 4; mi++) {
                    int row = a_row + mi * 16;
                    uint32_t addr = a_s + (uint32_t)(row * 128)
                                  + (uint32_t)((kb + a_csel) ^ ((row & 7) << 4));
                    LDMATRIX_X4(afr[nxt][mi][0], afr[nxt][mi][1],
                                afr[nxt][mi][2], afr[nxt][mi][3], addr);
                }
#pragma unroll
                for (int nj = 0; nj < 4; nj++) {
                    int row = b_row + nj * 16;
                    uint32_t addr = b_s + (uint32_t)(row * 128)
                                  + (uint32_t)((kb + b_csel) ^ ((row & 7) << 4));
                    uint32_t r0, r1, r2, r3;
                    LDMATRIX_X4(r0, r1, r2, r3, addr);
                    bfr[nxt][nj * 2][0] = r0;     bfr[nxt][nj * 2][1] = r1;
                    bfr[nxt][nj * 2 + 1][0] = r2; bfr[nxt][nj * 2 + 1][1] = r3;
                }
            }
#pragma unroll
            for (int mi = 0; mi < 4; mi++)
#pragma unroll
                for (int ni = 0; ni < 8; ni++)
                    mma16816(acc[mi][ni], afr[cur][mi], bfr[cur][ni]);
        }
    }

    // ===================== epilogue =====================
    // mma frag layout: c0,c1 -> (row = lane>>2, cols = 2*(lane&3), +1); c2,c3 -> row+8
    const int m0 = m_blk + warp_m * 64 + (lane >> 2);
    const int n0 = n_blk + warp_n * 64 + (lane & 3) * 2;
#pragma unroll
    for (int mi = 0; mi < 4; mi++) {
#pragma unroll
        for (int ni = 0; ni < 8; ni++) {
            float* p0 = out + (size_t)(m0 + mi * 16) * N_TOTAL + n0 + ni * 8;
            float* p1 = p0 + 8 * N_TOTAL;
            *(float2*)p0 = make_float2(acc[mi][ni][0], acc[mi][ni][1]);
            *(float2*)p1 = make_float2(acc[mi][ni][2], acc[mi][ni][3]);
        }
    }
}

// ===================== launch =====================
extern "C" void kernel_launch(void* const* d_in, const int* in_sizes, int n_in,
                              void* d_out, int out_size) {
    const float* x       = (const float*)d_in[0];   // [8192, 4096] f32
    const float* signs   = (const float*)d_in[1];   // [4096, 4096] f32 (+-1)
    const float* ps      = (const float*)d_in[2];   // [8, 131072]  f32
    const float* routing = (const float*)d_in[3];   // [8]          f32
    float* out = (float*)d_out;                     // [8192, 4096] f32

    blend_kernel<<<GROUPS / 256, 256>>>(ps, routing);
    convert_x_kernel<<<(int)(((size_t)M_TOTAL * K_TOTAL / 4) / 256), 256>>>((const float4*)x);
    build_w_kernel<<<(int)(((size_t)N_TOTAL * K_TOTAL / 4) / 256), 256>>>((const float4*)signs);

    cudaFuncSetAttribute(gemm_kernel, cudaFuncAttributeMaxDynamicSharedMemorySize, SMEM_TOTAL);
    gemm_kernel<<<dim3(N_TOTAL / BN, M_TOTAL / BM, 1), 256, SMEM_TOTAL>>>(out);
}

// round 9
// speedup vs baseline: 1.1727x; 1.0585x over previous
#include <cuda_runtime.h>
#include <cuda_fp16.h>
#include <cstdint>

// ===================== problem constants =====================
static constexpr int M_TOTAL = 8192;     // B*S = 4*2048 tokens
static constexpr int N_TOTAL = 4096;     // out_features
static constexpr int K_TOTAL = 4096;     // in_features
static constexpr int GROUPS  = 131072;   // out*in/group_size

// ===================== GEMM tiling =====================
static constexpr int BM = 128;
static constexpr int BN = 128;
static constexpr int BK = 64;                       // fp16 elems; 128B row -> SW128 atom
static constexpr int NUM_K  = K_TOTAL / BK;         // 64
static constexpr int STAGES = 3;

static constexpr int A_BYTES     = BM * 128;        // 16 KB
static constexpr int B_BYTES     = BN * 128;        // 16 KB
static constexpr int STAGE_BYTES = A_BYTES + B_BYTES;  // 32 KB
static constexpr int SMEM_TOTAL  = 1024 + STAGES * STAGE_BYTES;  // ~97 KB -> 2 CTAs/SM

// ===================== scratch (no allocation allowed) =====================
__device__ __half g_x16[(size_t)M_TOTAL * K_TOTAL];   // 64 MB
__device__ __half g_w16[(size_t)N_TOTAL * K_TOTAL];   // 32 MB
__device__ float  g_blend[GROUPS];                    // 0.5 MB

// ===================== PTX helpers (baseline sm_80-class only) =====================
__device__ __forceinline__ uint32_t smem_u32(const void* p) {
    uint32_t a;
    asm("{ .reg .u64 t; cvta.to.shared.u64 t, %1; cvt.u32.u64 %0, t; }" : "=r"(a) : "l"(p));
    return a;
}
__device__ __forceinline__ void cp_async16(uint32_t dst, const void* src) {
    asm volatile("cp.async.cg.shared.global [%0], [%1], 16;" :: "r"(dst), "l"(src));
}
__device__ __forceinline__ void cp_commit() {
    asm volatile("cp.async.commit_group;" ::: "memory");
}
__device__ __forceinline__ void cp_wait_1() {
    asm volatile("cp.async.wait_group 1;" ::: "memory");
}

#define LDMATRIX_X4(r0, r1, r2, r3, addr) \
    asm volatile("ldmatrix.sync.aligned.m8n8.x4.shared.b16 {%0,%1,%2,%3}, [%4];" \
                 : "=r"(r0), "=r"(r1), "=r"(r2), "=r"(r3) : "r"(addr))

__device__ __forceinline__ void mma16816(float* c, const uint32_t* a, const uint32_t* b) {
    asm volatile(
        "mma.sync.aligned.m16n8k16.row.col.f32.f16.f16.f32 "
        "{%0,%1,%2,%3}, {%4,%5,%6,%7}, {%8,%9}, {%0,%1,%2,%3};"
        : "+f"(c[0]), "+f"(c[1]), "+f"(c[2]), "+f"(c[3])
        : "r"(a[0]), "r"(a[1]), "r"(a[2]), "r"(a[3]), "r"(b[0]), "r"(b[1]));
}

// SW128: cols < 128B so the xor value depends only on row&7
#define SW128(off) ((off) ^ (((off) >> 3) & 0x70))

// ===================== prep kernels =====================
__global__ void blend_kernel(const float* __restrict__ ps, const float* __restrict__ routing) {
    __shared__ float r[8];
    if (threadIdx.x < 8) r[threadIdx.x] = routing[threadIdx.x];
    __syncthreads();
    int g = blockIdx.x * blockDim.x + threadIdx.x;
    if (g < GROUPS) {
        float acc = 0.f;
#pragma unroll
        for (int p = 0; p < 8; p++) acc = fmaf(r[p], ps[(size_t)p * GROUPS + g], acc);
        g_blend[g] = acc;
    }
}

__global__ void convert_x_kernel(const float4* __restrict__ x) {
    size_t i = (size_t)blockIdx.x * blockDim.x + threadIdx.x;   // one float4 each
    const size_t n4 = (size_t)M_TOTAL * K_TOTAL / 4;
    if (i < n4) {
        float4 v = x[i];
        __half2* o = (__half2*)g_x16;
        o[2 * i]     = __floats2half2_rn(v.x, v.y);
        o[2 * i + 1] = __floats2half2_rn(v.z, v.w);
    }
}

__global__ void build_w_kernel(const float4* __restrict__ signs) {
    size_t i = (size_t)blockIdx.x * blockDim.x + threadIdx.x;   // one float4 each
    const size_t n4 = (size_t)N_TOTAL * K_TOTAL / 4;
    if (i < n4) {
        float4 s = signs[i];
        size_t e = i * 4;                 // e = o*4096 + c ; group = e >> 7
        float sc = g_blend[e >> 7];
        __half2* o = (__half2*)g_w16;
        o[2 * i]     = __floats2half2_rn(s.x * sc, s.y * sc);
        o[2 * i + 1] = __floats2half2_rn(s.z * sc, s.w * sc);
    }
}

// ===================== main GEMM kernel =====================
// 128 threads = 4 warps (2x2), warp tile 64x64; 2 CTAs/SM.
// Both A ([m][k]) and B ([n][k]) K-major fp16 -> ldmatrix non-trans for both,
// mma.m16n8k16.row.col, f32 accumulation. Fragments double-buffered across ksteps.
__device__ __forceinline__ void load_tiles(uint32_t a_s, uint32_t b_s,
                                           const __half* __restrict__ Ag,
                                           const __half* __restrict__ Bg,
                                           int kelem, int tid) {
#pragma unroll
    for (int t = 0; t < 8; t++) {        // A: 128 rows x 8 chunks(16B) = 1024 chunks
        int id = t * 128 + tid;
        int r = id >> 3, c = id & 7;
        uint32_t off = (uint32_t)(r * 128 + c * 16);
        cp_async16(a_s + SW128(off), Ag + (size_t)r * K_TOTAL + kelem + c * 8);
    }
#pragma unroll
    for (int t = 0; t < 8; t++) {        // B: 128 rows x 8 chunks = 1024 chunks
        int id = t * 128 + tid;
        int r = id >> 3, c = id & 7;
        uint32_t off = (uint32_t)(r * 128 + c * 16);
        cp_async16(b_s + SW128(off), Bg + (size_t)r * K_TOTAL + kelem + c * 8);
    }
}

__global__ void __launch_bounds__(128, 2)
gemm_kernel(float* __restrict__ out) {
    extern __shared__ char smem[];
    uint32_t raw  = smem_u32(smem);
    uint32_t base = (raw + 1023) & ~1023u;              // 1024-aligned tile area

    const int tid  = threadIdx.x;
    const int wid  = tid >> 5;
    const int lane = tid & 31;
    const int warp_m = wid & 1;          // 2 warps along M (64 rows each)
    const int warp_n = wid >> 1;         // 2 warps along N (64 cols each)

    const int m_blk = blockIdx.y * BM;
    const int n_blk = blockIdx.x * BN;

    const __half* Ag = g_x16 + (size_t)m_blk * K_TOTAL;
    const __half* Bg = g_w16 + (size_t)n_blk * K_TOTAL;

    float acc[4][8][4];
#pragma unroll
    for (int i = 0; i < 4; i++)
#pragma unroll
        for (int j = 0; j < 8; j++)
#pragma unroll
            for (int v = 0; v < 4; v++) acc[i][j][v] = 0.f;

    // prologue: fill STAGES-1 stages
#pragma unroll
    for (int s = 0; s < STAGES - 1; s++) {
        load_tiles(base + s * STAGE_BYTES, base + s * STAGE_BYTES + A_BYTES,
                   Ag, Bg, s * BK, tid);
        cp_commit();
    }

    // per-thread ldmatrix row indices (column byte varies per kstep)
    const int a_row  = warp_m * 64 + (lane & 15);                     // + mi*16
    const int a_csel = (lane >> 4) * 16;                              // 0 or 16 bytes
    const int b_row  = warp_n * 64 + ((lane >> 4) << 3) + (lane & 7); // + nj*16
    const int b_csel = ((lane >> 3) & 1) * 16;                        // 0 or 16 bytes

    uint32_t afr[2][4][4];
    uint32_t bfr[2][8][2];

    int st = 0;                  // stage being computed
    int ld_st = STAGES - 1;      // stage being loaded this iteration

    for (int k = 0; k < NUM_K; k++) {
        cp_wait_1();                      // stage k resident (<=1 group in flight)
        __syncthreads();                  // all warps done with previous stage reuse

        // prefetch stage k+STAGES-1 (overwrites stage k-1, freed by barrier above)
        const int nk = k + STAGES - 1;
        if (nk < NUM_K) {
            load_tiles(base + ld_st * STAGE_BYTES, base + ld_st * STAGE_BYTES + A_BYTES,
                       Ag, Bg, nk * BK, tid);
        }
        cp_commit();                      // empty groups in tail keep counts consistent
        ld_st = (ld_st + 1 == STAGES) ? 0 : ld_st + 1;

        const uint32_t a_s = base + st * STAGE_BYTES;
        const uint32_t b_s = a_s + A_BYTES;
        st = (st + 1 == STAGES) ? 0 : st + 1;

        // load fragments for kstep 0 into buffer 0
#pragma unroll
        for (int mi = 0; mi < 4; mi++) {
            int row = a_row + mi * 16;
            uint32_t addr = a_s + (uint32_t)(row * 128) + (uint32_t)((a_csel) ^ ((row & 7) << 4));
            LDMATRIX_X4(afr[0][mi][0], afr[0][mi][1], afr[0][mi][2], afr[0][mi][3], addr);
        }
#pragma unroll
        for (int nj = 0; nj < 4; nj++) {
            int row = b_row + nj * 16;
            uint32_t addr = b_s + (uint32_t)(row * 128) + (uint32_t)((b_csel) ^ ((row & 7) << 4));
            uint32_t r0, r1, r2, r3;
            LDMATRIX_X4(r0, r1, r2, r3, addr);
            bfr[0][nj * 2][0] = r0;     bfr[0][nj * 2][1] = r1;
            bfr[0][nj * 2 + 1][0] = r2; bfr[0][nj * 2 + 1][1] = r3;
        }

#pragma unroll
        for (int ks = 0; ks < 4; ks++) {
            const int cur = ks & 1;
            const int nxt = cur ^ 1;
            if (ks < 3) {
                const int kb = (ks + 1) * 32;   // byte offset along K
#pragma unroll
                for (int mi = 0; mi < 4; mi++) {
                    int row = a_row + mi * 16;
                    uint32_t addr = a_s + (uint32_t)(row * 128)
                                  + (uint32_t)((kb + a_csel) ^ ((row & 7) << 4));
                    LDMATRIX_X4(afr[nxt][mi][0], afr[nxt][mi][1],
                                afr[nxt][mi][2], afr[nxt][mi][3], addr);
                }
#pragma unroll
                for (int nj = 0; nj < 4; nj++) {
                    int row = b_row + nj * 16;
                    uint32_t addr = b_s + (uint32_t)(row * 128)
                                  + (uint32_t)((kb + b_csel) ^ ((row & 7) << 4));
                    uint32_t r0, r1, r2, r3;
                    LDMATRIX_X4(r0, r1, r2, r3, addr);
                    bfr[nxt][nj * 2][0] = r0;     bfr[nxt][nj * 2][1] = r1;
                    bfr[nxt][nj * 2 + 1][0] = r2; bfr[nxt][nj * 2 + 1][1] = r3;
                }
            }
#pragma unroll
            for (int mi = 0; mi < 4; mi++)
#pragma unroll
                for (int ni = 0; ni < 8; ni++)
                    mma16816(acc[mi][ni], afr[cur][mi], bfr[cur][ni]);
        }
    }

    // ===================== epilogue =====================
    // mma frag layout: c0,c1 -> (row = lane>>2, cols = 2*(lane&3), +1); c2,c3 -> row+8
    const int m0 = m_blk + warp_m * 64 + (lane >> 2);
    const int n0 = n_blk + warp_n * 64 + (lane & 3) * 2;
#pragma unroll
    for (int mi = 0; mi < 4; mi++) {
#pragma unroll
        for (int ni = 0; ni < 8; ni++) {
            float* p0 = out + (size_t)(m0 + mi * 16) * N_TOTAL + n0 + ni * 8;
            float* p1 = p0 + 8 * N_TOTAL;
            *(float2*)p0 = make_float2(acc[mi][ni][0], acc[mi][ni][1]);
            *(float2*)p1 = make_float2(acc[mi][ni][2], acc[mi][ni][3]);
        }
    }
}

// ===================== launch =====================
extern "C" void kernel_launch(void* const* d_in, const int* in_sizes, int n_in,
                              void* d_out, int out_size) {
    const float* x       = (const float*)d_in[0];   // [8192, 4096] f32
    const float* signs   = (const float*)d_in[1];   // [4096, 4096] f32 (+-1)
    const float* ps      = (const float*)d_in[2];   // [8, 131072]  f32
    const float* routing = (const float*)d_in[3];   // [8]          f32
    float* out = (float*)d_out;                     // [8192, 4096] f32

    blend_kernel<<<GROUPS / 256, 256>>>(ps, routing);
    convert_x_kernel<<<(int)(((size_t)M_TOTAL * K_TOTAL / 4) / 256), 256>>>((const float4*)x);
    build_w_kernel<<<(int)(((size_t)N_TOTAL * K_TOTAL / 4) / 256), 256>>>((const float4*)signs);

    cudaFuncSetAttribute(gemm_kernel, cudaFuncAttributeMaxDynamicSharedMemorySize, SMEM_TOTAL);
    gemm_kernel<<<dim3(N_TOTAL / BN, M_TOTAL / BM, 1), 128, SMEM_TOTAL>>>(out);
}

// round 10
// speedup vs baseline: 1.3918x; 1.1869x over previous
#include <cuda_runtime.h>
#include <cuda_fp16.h>
#include <cstdint>

// ===================== problem constants =====================
static constexpr int M_TOTAL = 8192;     // B*S = 4*2048 tokens
static constexpr int N_TOTAL = 4096;     // out_features
static constexpr int K_TOTAL = 4096;     // in_features
static constexpr int GROUPS  = 131072;   // out*in/group_size

// ===================== GEMM tiling =====================
static constexpr int BM = 128;
static constexpr int BN = 128;
static constexpr int BK = 64;                       // fp16 elems; 128B row -> SW128 atom
static constexpr int NUM_K  = K_TOTAL / BK;         // 64
static constexpr int STAGES = 3;

static constexpr int A_BYTES     = BM * 128;        // 16 KB
static constexpr int B_BYTES     = BN * 128;        // 16 KB
static constexpr int STAGE_BYTES = A_BYTES + B_BYTES;  // 32 KB
static constexpr int SMEM_TOTAL  = 1024 + STAGES * STAGE_BYTES;  // ~97 KB -> 2 CTAs/SM

// ===================== scratch (no allocation allowed) =====================
__device__ __half g_x16[(size_t)M_TOTAL * K_TOTAL];   // 64 MB
__device__ __half g_w16[(size_t)N_TOTAL * K_TOTAL];   // 32 MB
__device__ float  g_blend[GROUPS];                    // 0.5 MB

// ===================== PTX helpers (baseline sm_80-class only) =====================
__device__ __forceinline__ uint32_t smem_u32(const void* p) {
    uint32_t a;
    asm("{ .reg .u64 t; cvta.to.shared.u64 t, %1; cvt.u32.u64 %0, t; }" : "=r"(a) : "l"(p));
    return a;
}
__device__ __forceinline__ void cp_async16(uint32_t dst, const void* src) {
    asm volatile("cp.async.cg.shared.global [%0], [%1], 16;" :: "r"(dst), "l"(src));
}
__device__ __forceinline__ void cp_commit() {
    asm volatile("cp.async.commit_group;" ::: "memory");
}
__device__ __forceinline__ void cp_wait_1() {
    asm volatile("cp.async.wait_group 1;" ::: "memory");
}

#define LDMATRIX_X4(r0, r1, r2, r3, addr) \
    asm volatile("ldmatrix.sync.aligned.m8n8.x4.shared.b16 {%0,%1,%2,%3}, [%4];" \
                 : "=r"(r0), "=r"(r1), "=r"(r2), "=r"(r3) : "r"(addr))

__device__ __forceinline__ void mma16816(float* c, const uint32_t* a, const uint32_t* b) {
    asm volatile(
        "mma.sync.aligned.m16n8k16.row.col.f32.f16.f16.f32 "
        "{%0,%1,%2,%3}, {%4,%5,%6,%7}, {%8,%9}, {%0,%1,%2,%3};"
        : "+f"(c[0]), "+f"(c[1]), "+f"(c[2]), "+f"(c[3])
        : "r"(a[0]), "r"(a[1]), "r"(a[2]), "r"(a[3]), "r"(b[0]), "r"(b[1]));
}

// SW128: cols < 128B so the xor value depends only on row&7
#define SW128(off) ((off) ^ (((off) >> 3) & 0x70))

// ===================== prep kernels =====================
__global__ void blend_kernel(const float* __restrict__ ps, const float* __restrict__ routing) {
    __shared__ float r[8];
    if (threadIdx.x < 8) r[threadIdx.x] = routing[threadIdx.x];
    __syncthreads();
    int g = blockIdx.x * blockDim.x + threadIdx.x;
    if (g < GROUPS) {
        float acc = 0.f;
#pragma unroll
        for (int p = 0; p < 8; p++) acc = fmaf(r[p], ps[(size_t)p * GROUPS + g], acc);
        g_blend[g] = acc;
    }
}

__global__ void convert_x_kernel(const float4* __restrict__ x) {
    size_t i = (size_t)blockIdx.x * blockDim.x + threadIdx.x;   // one float4 each
    const size_t n4 = (size_t)M_TOTAL * K_TOTAL / 4;
    if (i < n4) {
        float4 v = x[i];
        __half2* o = (__half2*)g_x16;
        o[2 * i]     = __floats2half2_rn(v.x, v.y);
        o[2 * i + 1] = __floats2half2_rn(v.z, v.w);
    }
}

__global__ void build_w_kernel(const float4* __restrict__ signs) {
    size_t i = (size_t)blockIdx.x * blockDim.x + threadIdx.x;   // one float4 each
    const size_t n4 = (size_t)N_TOTAL * K_TOTAL / 4;
    if (i < n4) {
        float4 s = signs[i];
        size_t e = i * 4;                 // e = o*4096 + c ; group = e >> 7
        float sc = g_blend[e >> 7];
        __half2* o = (__half2*)g_w16;
        o[2 * i]     = __floats2half2_rn(s.x * sc, s.y * sc);
        o[2 * i + 1] = __floats2half2_rn(s.z * sc, s.w * sc);
    }
}

// ===================== main GEMM kernel =====================
// 128 threads = 4 warps (2x2), warp tile 64x64; 2 CTAs/SM; 3-stage cp.async pipeline.
// Cross-barrier fragment preloading: the wait+sync happens BEFORE the last kstep of
// each iteration, and the next iteration's kstep-0 fragments are LDSM'd immediately
// after the sync so MMAs issue back-to-back across the iteration boundary.
__device__ __forceinline__ void load_tiles(uint32_t a_s, uint32_t b_s,
                                           const __half* __restrict__ Ag,
                                           const __half* __restrict__ Bg,
                                           int kelem, int tid) {
#pragma unroll
    for (int t = 0; t < 8; t++) {        // A: 128 rows x 8 chunks(16B) = 1024 chunks
        int id = t * 128 + tid;
        int r = id >> 3, c = id & 7;
        uint32_t off = (uint32_t)(r * 128 + c * 16);
        cp_async16(a_s + SW128(off), Ag + (size_t)r * K_TOTAL + kelem + c * 8);
    }
#pragma unroll
    for (int t = 0; t < 8; t++) {        // B: 128 rows x 8 chunks = 1024 chunks
        int id = t * 128 + tid;
        int r = id >> 3, c = id & 7;
        uint32_t off = (uint32_t)(r * 128 + c * 16);
        cp_async16(b_s + SW128(off), Bg + (size_t)r * K_TOTAL + kelem + c * 8);
    }
}

__global__ void __launch_bounds__(128, 2)
gemm_kernel(float* __restrict__ out) {
    extern __shared__ char smem[];
    uint32_t raw  = smem_u32(smem);
    uint32_t base = (raw + 1023) & ~1023u;              // 1024-aligned tile area

    const int tid  = threadIdx.x;
    const int wid  = tid >> 5;
    const int lane = tid & 31;
    const int warp_m = wid & 1;          // 2 warps along M (64 rows each)
    const int warp_n = wid >> 1;         // 2 warps along N (64 cols each)

    const int m_blk = blockIdx.y * BM;
    const int n_blk = blockIdx.x * BN;

    const __half* Ag = g_x16 + (size_t)m_blk * K_TOTAL;
    const __half* Bg = g_w16 + (size_t)n_blk * K_TOTAL;

    float acc[4][8][4];
#pragma unroll
    for (int i = 0; i < 4; i++)
#pragma unroll
        for (int j = 0; j < 8; j++)
#pragma unroll
            for (int v = 0; v < 4; v++) acc[i][j][v] = 0.f;

    // per-thread ldmatrix row indices (column byte varies per kstep)
    const int a_row  = warp_m * 64 + (lane & 15);                     // + mi*16
    const int a_csel = (lane >> 4) * 16;                              // 0 or 16 bytes
    const int b_row  = warp_n * 64 + ((lane >> 4) << 3) + (lane & 7); // + nj*16
    const int b_csel = ((lane >> 3) & 1) * 16;                        // 0 or 16 bytes

    uint32_t afr[2][4][4];
    uint32_t bfr[2][8][2];

    // fragment preload for one kstep into buffer `buf` from stage base (a_s,b_s)
#define PRELOAD_FRAGS(buf, a_s_, b_s_, kb)                                            \
    do {                                                                              \
        _Pragma("unroll")                                                             \
        for (int mi = 0; mi < 4; mi++) {                                              \
            int row = a_row + mi * 16;                                                \
            uint32_t addr = (a_s_) + (uint32_t)(row * 128)                            \
                          + (uint32_t)(((kb) + a_csel) ^ ((row & 7) << 4));           \
            LDMATRIX_X4(afr[buf][mi][0], afr[buf][mi][1],                             \
                        afr[buf][mi][2], afr[buf][mi][3], addr);                      \
        }                                                                             \
        _Pragma("unroll")                                                             \
        for (int nj = 0; nj < 4; nj++) {                                              \
            int row = b_row + nj * 16;                                                \
            uint32_t addr = (b_s_) + (uint32_t)(row * 128)                            \
                          + (uint32_t)(((kb) + b_csel) ^ ((row & 7) << 4));           \
            uint32_t r0, r1, r2, r3;                                                  \
            LDMATRIX_X4(r0, r1, r2, r3, addr);                                        \
            bfr[buf][nj * 2][0] = r0;     bfr[buf][nj * 2][1] = r1;                   \
            bfr[buf][nj * 2 + 1][0] = r2; bfr[buf][nj * 2 + 1][1] = r3;               \
        }                                                                             \
    } while (0)

#define MMA_KSTEP(buf)                                                                \
    do {                                                                              \
        _Pragma("unroll")                                                             \
        for (int mi = 0; mi < 4; mi++)                                                \
            _Pragma("unroll")                                                         \
            for (int ni = 0; ni < 8; ni++)                                            \
                mma16816(acc[mi][ni], afr[buf][mi], bfr[buf][ni]);                    \
    } while (0)

    // prologue: load stages 0 and 1, make stage 0 visible, preload its kstep-0 frags
    load_tiles(base, base + A_BYTES, Ag, Bg, 0, tid);
    cp_commit();
    load_tiles(base + STAGE_BYTES, base + STAGE_BYTES + A_BYTES, Ag, Bg, BK, tid);
    cp_commit();
    cp_wait_1();                 // stage 0 complete (groups retire in order)
    __syncthreads();             // stage 0 visible to all warps
    PRELOAD_FRAGS(0, base, base + A_BYTES, 0);

    int cur_st = 0;              // stage computed this iteration
    int ld_st  = 2;              // stage loaded this iteration (holds k+2)

    for (int k = 0; k < NUM_K; k++) {
        // issue loads for iteration k+2 (stage ld_st was last read at iter k-1,
        // and every warp passed the end-of-(k-1) barrier before reaching here)
        const int nk = k + 2;
        const uint32_t l_s = base + ld_st * STAGE_BYTES;
        if (nk < NUM_K) {
            load_tiles(l_s, l_s + A_BYTES, Ag, Bg, nk * BK, tid);
        }
        cp_commit();             // one group per iteration (possibly empty near tail)
        ld_st = (ld_st + 1 == STAGES) ? 0 : ld_st + 1;

        const uint32_t a_s = base + cur_st * STAGE_BYTES;
        const uint32_t b_s = a_s + A_BYTES;
        cur_st = (cur_st + 1 == STAGES) ? 0 : cur_st + 1;
        const uint32_t a_sn = base + cur_st * STAGE_BYTES;   // next stage
        const uint32_t b_sn = a_sn + A_BYTES;

        // ksteps 0..2: preload next kstep's frags, then MMA
        PRELOAD_FRAGS(1, a_s, b_s, 32);      // kstep 1
        MMA_KSTEP(0);                        // kstep 0
        PRELOAD_FRAGS(0, a_s, b_s, 64);      // kstep 2
        MMA_KSTEP(1);                        // kstep 1
        PRELOAD_FRAGS(1, a_s, b_s, 96);      // kstep 3
        MMA_KSTEP(0);                        // kstep 2

        // cross-barrier preload: make stage k+1 visible, grab its kstep-0 frags,
        // then run kstep 3's MMAs (which cover the LDSM latency).
        cp_wait_1();             // pending: {load(k+1), load(k+2)} -> retires load(k+1)
        __syncthreads();         // stage k+1 visible; also gates reuse of stage (k-1)%3
        if (k + 1 < NUM_K) {
            PRELOAD_FRAGS(0, a_sn, b_sn, 0); // next iteration's kstep 0
        }
        MMA_KSTEP(1);                        // kstep 3
    }

    // ===================== epilogue =====================
    // mma frag layout: c0,c1 -> (row = lane>>2, cols = 2*(lane&3), +1); c2,c3 -> row+8
    const int m0 = m_blk + warp_m * 64 + (lane >> 2);
    const int n0 = n_blk + warp_n * 64 + (lane & 3) * 2;
#pragma unroll
    for (int mi = 0; mi < 4; mi++) {
#pragma unroll
        for (int ni = 0; ni < 8; ni++) {
            float* p0 = out + (size_t)(m0 + mi * 16) * N_TOTAL + n0 + ni * 8;
            float* p1 = p0 + 8 * N_TOTAL;
            *(float2*)p0 = make_float2(acc[mi][ni][0], acc[mi][ni][1]);
            *(float2*)p1 = make_float2(acc[mi][ni][2], acc[mi][ni][3]);
        }
    }
#undef PRELOAD_FRAGS
#undef MMA_KSTEP
}

// ===================== launch =====================
extern "C" void kernel_launch(void* const* d_in, const int* in_sizes, int n_in,
                              void* d_out, int out_size) {
    const float* x       = (const float*)d_in[0];   // [8192, 4096] f32
    const float* signs   = (const float*)d_in[1];   // [4096, 4096] f32 (+-1)
    const float* ps      = (const float*)d_in[2];   // [8, 131072]  f32
    const float* routing = (const float*)d_in[3];   // [8]          f32
    float* out = (float*)d_out;                     // [8192, 4096] f32

    blend_kernel<<<GROUPS / 256, 256>>>(ps, routing);
    convert_x_kernel<<<(int)(((size_t)M_TOTAL * K_TOTAL / 4) / 256), 256>>>((const float4*)x);
    build_w_kernel<<<(int)(((size_t)N_TOTAL * K_TOTAL / 4) / 256), 256>>>((const float4*)signs);

    cudaFuncSetAttribute(gemm_kernel, cudaFuncAttributeMaxDynamicSharedMemorySize, SMEM_TOTAL);
    gemm_kernel<<<dim3(N_TOTAL / BN, M_TOTAL / BM, 1), 128, SMEM_TOTAL>>>(out);
}

// round 13
// speedup vs baseline: 1.3979x; 1.0043x over previous
#include <cuda_runtime.h>
#include <cuda_fp16.h>
#include <cstdint>

// ===================== problem constants =====================
static constexpr int M_TOTAL = 8192;     // B*S = 4*2048 tokens
static constexpr int N_TOTAL = 4096;     // out_features
static constexpr int K_TOTAL = 4096;     // in_features
static constexpr int GROUPS  = 131072;   // out*in/group_size

// ===================== GEMM tiling =====================
static constexpr int BM = 128;
static constexpr int BN = 128;
static constexpr int BK = 64;                       // fp16 elems; 128B row -> SW128 atom
static constexpr int NUM_K  = K_TOTAL / BK;         // 64
static constexpr int STAGES = 3;

static constexpr int A_BYTES     = BM * 128;        // 16 KB
static constexpr int B_BYTES     = BN * 128;        // 16 KB
static constexpr int STAGE_BYTES = A_BYTES + B_BYTES;  // 32 KB
static constexpr int SMEM_TOTAL  = 1024 + STAGES * STAGE_BYTES;  // ~97 KB -> 2 CTAs/SM

// ===================== scratch (no allocation allowed) =====================
__device__ __half g_x16[(size_t)M_TOTAL * K_TOTAL];   // 64 MB
__device__ __half g_w16[(size_t)N_TOTAL * K_TOTAL];   // 32 MB
__device__ float  g_blend[GROUPS];                    // 0.5 MB

// ===================== PTX helpers (baseline sm_80-class only) =====================
__device__ __forceinline__ uint32_t smem_u32(const void* p) {
    uint32_t a;
    asm("{ .reg .u64 t; cvta.to.shared.u64 t, %1; cvt.u32.u64 %0, t; }" : "=r"(a) : "l"(p));
    return a;
}
__device__ __forceinline__ void cp_async16(uint32_t dst, const void* src) {
    asm volatile("cp.async.cg.shared.global [%0], [%1], 16;" :: "r"(dst), "l"(src));
}
__device__ __forceinline__ void cp_commit() {
    asm volatile("cp.async.commit_group;" ::: "memory");
}
__device__ __forceinline__ void cp_wait_1() {
    asm volatile("cp.async.wait_group 1;" ::: "memory");
}

#define LDMATRIX_X4(r0, r1, r2, r3, addr) \
    asm volatile("ldmatrix.sync.aligned.m8n8.x4.shared.b16 {%0,%1,%2,%3}, [%4];" \
                 : "=r"(r0), "=r"(r1), "=r"(r2), "=r"(r3) : "r"(addr))

__device__ __forceinline__ void mma16816(float* c, const uint32_t* a, const uint32_t* b) {
    asm volatile(
        "mma.sync.aligned.m16n8k16.row.col.f32.f16.f16.f32 "
        "{%0,%1,%2,%3}, {%4,%5,%6,%7}, {%8,%9}, {%0,%1,%2,%3};"
        : "+f"(c[0]), "+f"(c[1]), "+f"(c[2]), "+f"(c[3])
        : "r"(a[0]), "r"(a[1]), "r"(a[2]), "r"(a[3]), "r"(b[0]), "r"(b[1]));
}

// SW128: cols < 128B so the xor value depends only on row&7
#define SW128(off) ((off) ^ (((off) >> 3) & 0x70))

// ===================== prep kernels =====================
__global__ void blend_kernel(const float* __restrict__ ps, const float* __restrict__ routing) {
    __shared__ float r[8];
    if (threadIdx.x < 8) r[threadIdx.x] = routing[threadIdx.x];
    __syncthreads();
    int g = blockIdx.x * blockDim.x + threadIdx.x;
    if (g < GROUPS) {
        float acc = 0.f;
#pragma unroll
        for (int p = 0; p < 8; p++) acc = fmaf(r[p], ps[(size_t)p * GROUPS + g], acc);
        g_blend[g] = acc;
    }
}

// fused: x fp32->fp16 AND w = signs * blended (flat index over both tasks)
static constexpr size_t N4_X = (size_t)M_TOTAL * K_TOTAL / 4;   // 8M float4
static constexpr size_t N4_W = (size_t)N_TOTAL * K_TOTAL / 4;   // 4M float4

__global__ void prep_kernel(const float4* __restrict__ x, const float4* __restrict__ signs) {
    size_t i = (size_t)blockIdx.x * blockDim.x + threadIdx.x;
    if (i < N4_X) {
        float4 v = x[i];
        __half2* o = (__half2*)g_x16;
        o[2 * i]     = __floats2half2_rn(v.x, v.y);
        o[2 * i + 1] = __floats2half2_rn(v.z, v.w);
    } else if (i < N4_X + N4_W) {
        size_t j = i - N4_X;
        float4 s = signs[j];
        size_t e = j * 4;                 // e = o*4096 + c ; group = e >> 7
        float sc = g_blend[e >> 7];
        __half2* o = (__half2*)g_w16;
        o[2 * j]     = __floats2half2_rn(s.x * sc, s.y * sc);
        o[2 * j + 1] = __floats2half2_rn(s.z * sc, s.w * sc);
    }
}

// ===================== main GEMM kernel =====================
// 128 threads = 4 warps (2x2), warp tile 64x64; 2 CTAs/SM; 3-stage cp.async pipeline.
// Cross-barrier fragment preloading + cp.async issue spread across the 4 ksteps.
// Loads a quarter-tile (4 cp.async/thread): q=0,1 -> A half-rows; q=2,3 -> B half-rows
__device__ __forceinline__ void load_quarter(uint32_t a_s, uint32_t b_s,
                                             const __half* __restrict__ Ag,
                                             const __half* __restrict__ Bg,
                                             int kelem, int tid, int q) {
    const __half* G = (q < 2) ? Ag : Bg;
    uint32_t s_base  = (q < 2) ? a_s : b_s;
    int row_ofs = (q & 1) * 64;          // rows 0-63 or 64-127
#pragma unroll
    for (int t = 0; t < 4; t++) {        // 64 rows x 8 chunks(16B) = 512 chunks / 128 thr
        int id = t * 128 + tid;
        int r = row_ofs + (id >> 3), c = id & 7;
        uint32_t off = (uint32_t)(r * 128 + c * 16);
        cp_async16(s_base + SW128(off), G + (size_t)r * K_TOTAL + kelem + c * 8);
    }
}

__global__ void __launch_bounds__(128, 2)
gemm_kernel(float* __restrict__ out) {
    extern __shared__ char smem[];
    uint32_t raw  = smem_u32(smem);
    uint32_t base = (raw + 1023) & ~1023u;              // 1024-aligned tile area

    const int tid  = threadIdx.x;
    const int wid  = tid >> 5;
    const int lane = tid & 31;
    const int warp_m = wid & 1;          // 2 warps along M (64 rows each)
    const int warp_n = wid >> 1;         // 2 warps along N (64 cols each)

    const int m_blk = blockIdx.y * BM;
    const int n_blk = blockIdx.x * BN;

    const __half* Ag = g_x16 + (size_t)m_blk * K_TOTAL;
    const __half* Bg = g_w16 + (size_t)n_blk * K_TOTAL;

    float acc[4][8][4];
#pragma unroll
    for (int i = 0; i < 4; i++)
#pragma unroll
        for (int j = 0; j < 8; j++)
#pragma unroll
            for (int v = 0; v < 4; v++) acc[i][j][v] = 0.f;

    // per-thread ldmatrix row indices (column byte varies per kstep)
    const int a_row  = warp_m * 64 + (lane & 15);                     // + mi*16
    const int a_csel = (lane >> 4) * 16;                              // 0 or 16 bytes
    const int b_row  = warp_n * 64 + ((lane >> 4) << 3) + (lane & 7); // + nj*16
    const int b_csel = ((lane >> 3) & 1) * 16;                        // 0 or 16 bytes

    uint32_t afr[2][4][4];
    uint32_t bfr[2][8][2];

#define PRELOAD_FRAGS(buf, a_s_, b_s_, kb)                                            \
    do {                                                                              \
        _Pragma("unroll")                                                             \
        for (int mi = 0; mi < 4; mi++) {                                              \
            int row = a_row + mi * 16;                                                \
            uint32_t addr = (a_s_) + (uint32_t)(row * 128)                            \
                          + (uint32_t)(((kb) + a_csel) ^ ((row & 7) << 4));           \
            LDMATRIX_X4(afr[buf][mi][0], afr[buf][mi][1],                             \
                        afr[buf][mi][2], afr[buf][mi][3], addr);                      \
        }                                                                             \
        _Pragma("unroll")                                                             \
        for (int nj = 0; nj < 4; nj++) {                                              \
            int row = b_row + nj * 16;                                                \
            uint32_t addr = (b_s_) + (uint32_t)(row * 128)                            \
                          + (uint32_t)(((kb) + b_csel) ^ ((row & 7) << 4));           \
            uint32_t r0, r1, r2, r3;                                                  \
            LDMATRIX_X4(r0, r1, r2, r3, addr);                                        \
            bfr[buf][nj * 2][0] = r0;     bfr[buf][nj * 2][1] = r1;                   \
            bfr[buf][nj * 2 + 1][0] = r2; bfr[buf][nj * 2 + 1][1] = r3;               \
        }                                                                             \
    } while (0)

#define MMA_KSTEP(buf)                                                                \
    do {                                                                              \
        _Pragma("unroll")                                                             \
        for (int mi = 0; mi < 4; mi++)                                                \
            _Pragma("unroll")                                                         \
            for (int ni = 0; ni < 8; ni++)                                            \
                mma16816(acc[mi][ni], afr[buf][mi], bfr[buf][ni]);                    \
    } while (0)

    // prologue: load stages 0 and 1, make stage 0 visible, preload its kstep-0 frags
#pragma unroll
    for (int q = 0; q < 4; q++) load_quarter(base, base + A_BYTES, Ag, Bg, 0, tid, q);
    cp_commit();
#pragma unroll
    for (int q = 0; q < 4; q++)
        load_quarter(base + STAGE_BYTES, base + STAGE_BYTES + A_BYTES, Ag, Bg, BK, tid, q);
    cp_commit();
    cp_wait_1();                 // stage 0 complete (groups retire in order)
    __syncthreads();             // stage 0 visible to all warps
    PRELOAD_FRAGS(0, base, base + A_BYTES, 0);

    int cur_st = 0;              // stage computed this iteration
    int ld_st  = 2;              // stage loaded this iteration (holds k+2)

    for (int k = 0; k < NUM_K; k++) {
        const int nk = k + 2;
        const bool do_load = (nk < NUM_K);
        const uint32_t la_s = base + ld_st * STAGE_BYTES;
        const uint32_t lb_s = la_s + A_BYTES;
        const int lkel = nk * BK;
        ld_st = (ld_st + 1 == STAGES) ? 0 : ld_st + 1;

        const uint32_t a_s = base + cur_st * STAGE_BYTES;
        const uint32_t b_s = a_s + A_BYTES;
        cur_st = (cur_st + 1 == STAGES) ? 0 : cur_st + 1;
        const uint32_t a_sn = base + cur_st * STAGE_BYTES;   // next stage
        const uint32_t b_sn = a_sn + A_BYTES;

        // ksteps 0..2: preload next kstep frags, MMA, and a quarter of load(k+2)
        PRELOAD_FRAGS(1, a_s, b_s, 32);      // kstep 1 frags
        if (do_load) load_quarter(la_s, lb_s, Ag, Bg, lkel, tid, 0);
        MMA_KSTEP(0);                        // kstep 0

        PRELOAD_FRAGS(0, a_s, b_s, 64);      // kstep 2 frags
        if (do_load) load_quarter(la_s, lb_s, Ag, Bg, lkel, tid, 1);
        MMA_KSTEP(1);                        // kstep 1

        PRELOAD_FRAGS(1, a_s, b_s, 96);      // kstep 3 frags
        if (do_load) load_quarter(la_s, lb_s, Ag, Bg, lkel, tid, 2);
        MMA_KSTEP(0);                        // kstep 2

        if (do_load) load_quarter(la_s, lb_s, Ag, Bg, lkel, tid, 3);
        cp_commit();             // load(k+2) committed (possibly empty near tail)

        // cross-barrier preload: make stage k+1 visible, grab its kstep-0 frags,
        // then run kstep 3's MMAs (which cover the LDSM latency).
        cp_wait_1();             // pending: {load(k+1), load(k+2)} -> retires load(k+1)
        __syncthreads();         // stage k+1 visible; also gates reuse of stage (k-1)%3
        if (k + 1 < NUM_K) {
            PRELOAD_FRAGS(0, a_sn, b_sn, 0); // next iteration's kstep 0
        }
        MMA_KSTEP(1);                        // kstep 3
    }

    // ===================== epilogue =====================
    // mma frag layout: c0,c1 -> (row = lane>>2, cols = 2*(lane&3), +1); c2,c3 -> row+8
    const int m0 = m_blk + warp_m * 64 + (lane >> 2);
    const int n0 = n_blk + warp_n * 64 + (lane & 3) * 2;
#pragma unroll
    for (int mi = 0; mi < 4; mi++) {
#pragma unroll
        for (int ni = 0; ni < 8; ni++) {
            float* p0 = out + (size_t)(m0 + mi * 16) * N_TOTAL + n0 + ni * 8;
            float* p1 = p0 + 8 * N_TOTAL;
            *(float2*)p0 = make_float2(acc[mi][ni][0], acc[mi][ni][1]);
            *(float2*)p1 = make_float2(acc[mi][ni][2], acc[mi][ni][3]);
        }
    }
#undef PRELOAD_FRAGS
#undef MMA_KSTEP
}

// ===================== launch =====================
extern "C" void kernel_launch(void* const* d_in, const int* in_sizes, int n_in,
                              void* d_out, int out_size) {
    const float* x       = (const float*)d_in[0];   // [8192, 4096] f32
    const float* signs   = (const float*)d_in[1];   // [4096, 4096] f32 (+-1)
    const float* ps      = (const float*)d_in[2];   // [8, 131072]  f32
    const float* routing = (const float*)d_in[3];   // [8]          f32
    float* out = (float*)d_out;                     // [8192, 4096] f32

    blend_kernel<<<GROUPS / 256, 256>>>(ps, routing);
    prep_kernel<<<(int)((N4_X + N4_W + 255) / 256), 256>>>((const float4*)x, (const float4*)signs);

    cudaFuncSetAttribute(gemm_kernel, cudaFuncAttributeMaxDynamicSharedMemorySize, SMEM_TOTAL);
    gemm_kernel<<<dim3(N_TOTAL / BN, M_TOTAL / BM, 1), 128, SMEM_TOTAL>>>(out);
}